// round 7
// baseline (speedup 1.0000x reference)
#include <cuda_runtime.h>
#include <math.h>

#define BQ 8
#define HH 1024
#define WW 1024
#define HW (HH*WW)

// Scratch (device globals: allowed; no cudaMalloc anywhere)
__device__ float         d_gm [BQ*HW];   // 32 MB grad magnitude
__device__ unsigned char d_dir[BQ*HW];   //  8 MB orientation index (0..7)

extern __shared__ float smem_dyn[];

// ---------------------------------------------------------------------------
// K1: separable 5-tap gaussian blur (x3 channels -> smem planes) + fused
//     sobel + magnitude/orientation. 64x64 tile, 1024 threads, 4 px/thread.
// dyn smem: raw 70x72 + hblur 70x68 + 3 vblur planes 66x68  = 93,056 B
// (2 CTAs/SM -> 186 KB of 228 KB)
// ---------------------------------------------------------------------------
#define T1 64
#define RR 70   // raw rows/cols  (tile + 2*3 halo)
#define RP 72   // raw pitch
#define HC 66   // hblur cols     (tile + 2*1)
#define HP 68   // hblur pitch (70 rows)
#define VN 66   // vblur rows/cols
#define VP 68   // vblur pitch
#define OFF_H  (RR*RP)            // 5040
#define OFF_V  (OFF_H + RR*HP)    // 9800
#define VPL    (VN*VP)            // 4488 per plane
#define SMEM1  ((OFF_V + 3*VPL) * (int)sizeof(float))   // 93,056 B

__global__ __launch_bounds__(1024, 2)
void canny_grad(const float* __restrict__ img, const float* __restrict__ gw)
{
    float* s_raw = smem_dyn;            // [70][72]
    float* s_h   = smem_dyn + OFF_H;    // [70][68]
    float* s_v   = smem_dyn + OFF_V;    // [3][66][68]

    const int b   = blockIdx.z;
    const int ty0 = blockIdx.y * T1;
    const int tx0 = blockIdx.x * T1;
    const int tid = threadIdx.x;

    // exact reference weights; symmetric (g0==g4, g1==g3), center == 1.0 exact
    const float G0 = __ldg(&gw[0]);
    const float G1 = __ldg(&gw[1]);

    // true when raw halo AND blurred halo are entirely inside the image
    const bool interior = (ty0 >= 3) && (ty0 + T1 + 3 <= HH) &&
                          (tx0 >= 3) && (tx0 + T1 + 3 <= WW);

    // ---- Phase 1: blur each channel into its smem plane ----
    for (int c = 0; c < 3; ++c) {
        const float* im = img + (size_t)(b * 3 + c) * HW;

        // load raw 70x70 (zero pad OOB; fast path for interior blocks)
        if (interior) {
            const float* base = im + (size_t)(ty0 - 3) * WW + (tx0 - 3);
            #pragma unroll
            for (int k = 0; k < 5; ++k) {
                int i = tid + k * 1024;
                if (i < RR * RR) {
                    int r = i / RR, q = i - r * RR;
                    s_raw[r * RP + q] = __ldg(&base[r * WW + q]);
                }
            }
        } else {
            #pragma unroll
            for (int k = 0; k < 5; ++k) {
                int i = tid + k * 1024;
                if (i < RR * RR) {
                    int r = i / RR, q = i - r * RR;
                    int gh = ty0 - 3 + r, gx = tx0 - 3 + q;
                    float v = 0.f;
                    if ((unsigned)gh < HH && (unsigned)gx < WW)
                        v = __ldg(&im[gh * WW + gx]);
                    s_raw[r * RP + q] = v;
                }
            }
        }
        __syncthreads();

        // horizontal blur: 70 rows x 66 cols (symmetric taps, center weight 1)
        #pragma unroll
        for (int k = 0; k < 5; ++k) {
            int i = tid + k * 1024;
            if (i < RR * HC) {
                int r = i / HC, j = i - r * HC;
                const float* p = &s_raw[r * RP + j];
                s_h[r * HP + j] = (p[0] + p[4]) * G0 + (p[1] + p[3]) * G1 + p[2];
            }
        }
        __syncthreads();

        // vertical blur: 66 x 66 into plane c.
        // Reference applies sobel with ZERO padding on the BLURRED image, so
        // blurred samples outside [0,1024) must be forced to 0 (the blur of
        // the zero-padded raw image is nonzero there).  [audited R1, R3, R5]
        float* vp = s_v + c * VPL;
        #pragma unroll
        for (int k = 0; k < 5; ++k) {
            int i = tid + k * 1024;
            if (i < VN * HC) {
                int r = i / HC, j = i - r * HC;
                const float* p = &s_h[r * HP + j];
                float v = (p[0] + p[4*HP]) * G0 + (p[HP] + p[3*HP]) * G1 + p[2*HP];
                if (!interior) {
                    int gy_ = ty0 - 1 + r, gx_ = tx0 - 1 + j;
                    if ((unsigned)gy_ >= HH || (unsigned)gx_ >= WW) v = 0.f;
                }
                vp[r * VP + j] = v;
            }
        }
        __syncthreads();
    }

    // ---- Phase 2: sobel + magnitude + orientation, complete per pixel ----
    // (no accumulators live across barriers -> spill-free at 32-reg cap)
    #pragma unroll
    for (int k = 0; k < 4; ++k) {
        int pi = tid + k * 1024;
        int oy = pi >> 6, ox = pi & 63;
        float mag = 0.f, axs = 0.f, ays = 0.f;
        #pragma unroll
        for (int c = 0; c < 3; ++c) {
            const float* p = &s_v[c * VPL + oy * VP + ox];
            float a00 = p[0],      a01 = p[1],        a02 = p[2];
            float a10 = p[VP],                        a12 = p[VP + 2];
            float a20 = p[2*VP],   a21 = p[2*VP + 1], a22 = p[2*VP + 2];
            float gx = (a00 - a02) + 2.f * (a10 - a12) + (a20 - a22);
            float gy = (a00 - a20) + 2.f * (a01 - a21) + (a02 - a22);
            mag += sqrtf(gx * gx + gy * gy);
            axs += gx;
            ays += gy;
        }
        float deg = atan2f(ays, axs) * (float)(180.0 / M_PI) + 180.f;
        float r   = rintf(deg / 45.f);          // round-half-even = jnp.round
        int   idx = ((int)r) & 7;               // r in [0,8] integer; 8 -> 0
        size_t o  = (size_t)b * HW + (size_t)(ty0 + oy) * WW + (tx0 + ox);
        d_gm[o]  = mag;
        d_dir[o] = (unsigned char)idx;
    }
}

// ---------------------------------------------------------------------------
// K2: NMS (cross-batch gather via smem-resident 8-batch gm tile) + hysteresis
// 32x32 spatial tile, all 8 batches; 512 threads; dynamic smem ~80.7 KB
//
// Gather semantics (re-derived 3x): flat[idx*8HW + b*HW + h*W + w] means
//   sel_pos(b,h,w) = gm[idx ](h,w) - gm[idx ](h+dy_b, w+dx_b)
//   sel_neg(b,h,w) = gm[idx4](h,w) - gm[idx4](h+dy_b, w+dx_b)
// with (dy_b,dx_b) the cross-correlation offset of dir_f[b] (no kernel flip).
// ---------------------------------------------------------------------------
#define TS 32
#define GT 36   // gm tile extent (TS + 2*2 halo)
#define GP 37   // gm tile pitch
#define TT 34   // thin tile extent (TS + 2*1 halo)
#define TP 35   // thin tile pitch
#define SMEM2 ((8*GT*GP + 8*TT*TP) * (int)sizeof(float))   // 80,704 B

__constant__ int c_offy[8] = {0, 1, 1, 1, 0, -1, -1, -1};
__constant__ int c_offx[8] = {1, 1, 0, -1, -1, -1, 0, 1};

__global__ __launch_bounds__(512, 2)
void canny_thin(float* __restrict__ out)
{
    float* s_g = smem_dyn;                 // [8][36][37]
    float* s_t = smem_dyn + 8 * GT * GP;   // [8][34][35]

    const int ty0 = blockIdx.y * TS;
    const int tx0 = blockIdx.x * TS;
    const int tid = threadIdx.x;

    // load gm tiles for all 8 batches (zero pad OOB)
    for (int i = tid; i < 8 * GT * GT; i += 512) {
        int b   = i / (GT * GT);
        int rem = i - b * (GT * GT);
        int r = rem / GT, q = rem - r * GT;
        int gh = ty0 - 2 + r, gx = tx0 - 2 + q;
        float v = 0.f;
        if ((unsigned)gh < HH && (unsigned)gx < WW)
            v = d_gm[(size_t)b * HW + gh * WW + gx];
        s_g[(b * GT + r) * GP + q] = v;
    }
    __syncthreads();

    // thin (NMS) for tile + 1-halo, all batches
    for (int i = tid; i < 8 * TT * TT; i += 512) {
        int b   = i / (TT * TT);
        int rem = i - b * (TT * TT);
        int r = rem / TT, q = rem - r * TT;
        int gh = ty0 - 1 + r, gx = tx0 - 1 + q;
        float tval = 0.f;
        if ((unsigned)gh < HH && (unsigned)gx < WW) {
            int id  = d_dir[(size_t)b * HW + gh * WW + gx];
            int ip  = id;
            int in_ = (id + 4) & 7;
            int dy  = c_offy[b], dx = c_offx[b];
            int lr = r + 1, lq = q + 1;
            float cp = s_g[(ip  * GT + lr) * GP + lq];
            float cn = s_g[(in_ * GT + lr) * GP + lq];
            float np_ = 0.f, nn_ = 0.f;
            int nh = gh + dy, nw = gx + dx;
            if ((unsigned)nh < HH && (unsigned)nw < WW) {
                np_ = s_g[(ip  * GT + lr + dy) * GP + lq + dx];
                nn_ = s_g[(in_ * GT + lr + dy) * GP + lq + dx];
            }
            float sp = cp - np_;
            float sn = cn - nn_;
            if (fminf(sp, sn) > 0.f)
                tval = s_g[(b * GT + lr) * GP + lq];
        }
        s_t[(b * TT + r) * TP + q] = tval;
    }
    __syncthreads();

    // hysteresis + border zero, write output (streaming stores: out is
    // write-once; keep d_gm resident in L2 instead)
    for (int i = tid; i < 8 * TS * TS; i += 512) {
        int b   = i / (TS * TS);
        int rem = i - b * (TS * TS);
        int oy = rem / TS, ox = rem - oy * TS;
        int gh = ty0 + oy, gx = tx0 + ox;
        const float* tp = &s_t[(b * TT + oy) * TP + ox];
        float tc = tp[TP + 1];
        bool res = (tc > 5.0f);
        if (!res && tc >= 2.5f) {   // middle band (tc<=5 implied by !res)
            res = tp[0]      > 5.f || tp[1]        > 5.f || tp[2]        > 5.f ||
                  tp[TP]     > 5.f || tp[TP + 2]   > 5.f ||
                  tp[2*TP]   > 5.f || tp[2*TP + 1] > 5.f || tp[2*TP + 2] > 5.f;
        }
        bool interior = (gh > 0) && (gh < HH - 1) && (gx > 0) && (gx < WW - 1);
        __stcs(&out[(size_t)b * HW + gh * WW + gx], (res && interior) ? 1.0f : 0.0f);
    }
}

// ---------------------------------------------------------------------------
extern "C" void kernel_launch(void* const* d_in, const int* in_sizes, int n_in,
                              void* d_out, int out_size)
{
    const float* img = (const float*)d_in[0];
    const float* gw  = (const float*)d_in[1];   // gauss_h weights (5 floats)
    float* out = (float*)d_out;

    // opt-in to >48KB dynamic smem (idempotent; not an allocation)
    cudaFuncSetAttribute(canny_grad, cudaFuncAttributeMaxDynamicSharedMemorySize, SMEM1);
    cudaFuncSetAttribute(canny_thin, cudaFuncAttributeMaxDynamicSharedMemorySize, SMEM2);

    dim3 g1(WW / T1, HH / T1, BQ);     // 16 x 16 x 8
    canny_grad<<<g1, 1024, SMEM1>>>(img, gw);

    dim3 g2(WW / TS, HH / TS, 1);      // 32 x 32
    canny_thin<<<g2, 512, SMEM2>>>(out);
}

// round 9
// speedup vs baseline: 1.1617x; 1.1617x over previous
#include <cuda_runtime.h>
#include <math.h>

#define BQ 8
#define HH 1024
#define WW 1024
#define HW (HH*WW)

__device__ float         d_gm [BQ*HW];   // 32 MB grad magnitude
__device__ unsigned char d_dir[BQ*HW];   //  8 MB orientation index (0..7)

extern __shared__ float smem_dyn[];

// ---------------------------------------------------------------------------
// K1: separable 5-tap gaussian (3 channels -> smem planes) + fused sobel +
//     magnitude/orientation. 64x64 tile, 1024 threads, float4-vectorized.
// dyn smem: raw 70x72 + hblur 70x68 + 3 vblur planes 66x68 = 93,056 B
// Arithmetic is term-for-term identical to the R7 passing kernel.
// ---------------------------------------------------------------------------
#define T1 64
#define RR 70
#define RP 72
#define HP 68
#define VN 66
#define VP 68
#define NC4 17                       // float4 outputs per row (cols 0..67)
#define OFF_H  (RR*RP)               // 5040
#define OFF_V  (OFF_H + RR*HP)       // 9800
#define VPL    (VN*VP)               // 4488
#define SMEM1  ((OFF_V + 3*VPL) * (int)sizeof(float))   // 93,056

__global__ __launch_bounds__(1024, 2)
void canny_grad(const float* __restrict__ img, const float* __restrict__ gw)
{
    float* s_raw = smem_dyn;            // [70][72]
    float* s_h   = smem_dyn + OFF_H;    // [70][68]
    float* s_v   = smem_dyn + OFF_V;    // [3][66][68]

    const int b   = blockIdx.z;
    const int ty0 = blockIdx.y * T1;
    const int tx0 = blockIdx.x * T1;
    const int tid = threadIdx.x;
    const int lx  = tid & 63;
    const int ly  = tid >> 6;           // 0..15

    const float G0 = __ldg(&gw[0]);
    const float G1 = __ldg(&gw[1]);

    const bool interior = (ty0 >= 3) && (ty0 + T1 + 3 <= HH) &&
                          (tx0 >= 3) && (tx0 + T1 + 3 <= WW);

    for (int c = 0; c < 3; ++c) {
        const float* im = img + (size_t)(b * 3 + c) * HW;

        // ---- raw 70x70 load (structured, no div) ----
        if (interior) {
            const float* base = im + (size_t)(ty0 - 3) * WW + (tx0 - 3);
            #pragma unroll
            for (int k = 0; k < 5; ++k) {
                int r = ly + (k << 4);
                if (k < 4 || ly < 6) {
                    const float* src = base + r * WW;
                    float* dst = s_raw + r * RP;
                    dst[lx] = __ldg(src + lx);
                    if (lx < 6) dst[lx + 64] = __ldg(src + lx + 64);
                }
            }
        } else {
            #pragma unroll
            for (int k = 0; k < 5; ++k) {
                int r = ly + (k << 4);
                if (k < 4 || ly < 6) {
                    int gh = ty0 - 3 + r;
                    bool rok = (unsigned)gh < HH;
                    float* dst = s_raw + r * RP;
                    int gxx = tx0 - 3 + lx;
                    dst[lx] = (rok && (unsigned)gxx < WW)
                                ? __ldg(im + (size_t)gh * WW + gxx) : 0.f;
                    if (lx < 6) {
                        int q = lx + 64; gxx = tx0 - 3 + q;
                        dst[q] = (rok && (unsigned)gxx < WW)
                                   ? __ldg(im + (size_t)gh * WW + gxx) : 0.f;
                    }
                }
            }
        }
        __syncthreads();

        // ---- hblur, float4: 70 rows x 17 f4 (cols 66,67 garbage, never read)
        #pragma unroll
        for (int it = 0; it < 2; ++it) {
            int i = tid + (it << 10);
            if (i < RR * NC4) {
                int r = i / NC4, c4 = i - r * NC4;
                const float* p = s_raw + r * RP + (c4 << 2);
                float4 A = *(const float4*)p;
                float4 B = *(const float4*)(p + 4);
                float4 o;
                o.x = (A.x + B.x) * G0 + (A.y + A.w) * G1 + A.z;
                o.y = (A.y + B.y) * G0 + (A.z + B.x) * G1 + A.w;
                o.z = (A.z + B.z) * G0 + (A.w + B.y) * G1 + B.x;
                o.w = (A.w + B.w) * G0 + (B.x + B.z) * G1 + B.y;
                *(float4*)(s_h + r * HP + (c4 << 2)) = o;
            }
        }
        __syncthreads();

        // ---- vblur, float4: 66 rows x 17 f4; zero blurred-halo outside image
        float* vp = s_v + c * VPL;
        #pragma unroll
        for (int it = 0; it < 2; ++it) {
            int i = tid + (it << 10);
            if (i < VN * NC4) {
                int r = i / NC4, c4 = i - r * NC4;
                const float* p = s_h + r * HP + (c4 << 2);
                float4 a0 = *(const float4*)p;
                float4 a1 = *(const float4*)(p + HP);
                float4 a2 = *(const float4*)(p + 2*HP);
                float4 a3 = *(const float4*)(p + 3*HP);
                float4 a4 = *(const float4*)(p + 4*HP);
                float4 o;
                o.x = (a0.x + a4.x) * G0 + (a1.x + a3.x) * G1 + a2.x;
                o.y = (a0.y + a4.y) * G0 + (a1.y + a3.y) * G1 + a2.y;
                o.z = (a0.z + a4.z) * G0 + (a1.z + a3.z) * G1 + a2.z;
                o.w = (a0.w + a4.w) * G0 + (a1.w + a3.w) * G1 + a2.w;
                if (!interior) {
                    int gy_ = ty0 - 1 + r;
                    if ((unsigned)gy_ >= HH) { o.x = o.y = o.z = o.w = 0.f; }
                    else {
                        int gx0 = tx0 - 1 + (c4 << 2);
                        if ((unsigned)(gx0    ) >= WW) o.x = 0.f;
                        if ((unsigned)(gx0 + 1) >= WW) o.y = 0.f;
                        if ((unsigned)(gx0 + 2) >= WW) o.z = 0.f;
                        if ((unsigned)(gx0 + 3) >= WW) o.w = 0.f;
                    }
                }
                *(float4*)(vp + r * VP + (c4 << 2)) = o;
            }
        }
        __syncthreads();
    }

    // ---- sobel + mag + orientation: one float4 output per thread ----
    const int oy  = tid >> 4;           // 0..63
    const int ox4 = tid & 15;           // 0..15
    const int cb  = ox4 << 2;
    float mgv[4]; int ixi[4];

    #pragma unroll
    for (int h = 0; h < 2; ++h) {       // outputs j = 2h, 2h+1
        float m0 = 0.f, ax0 = 0.f, ay0 = 0.f;
        float m1 = 0.f, ax1 = 0.f, ay1 = 0.f;
        #pragma unroll
        for (int c = 0; c < 3; ++c) {
            const float* p = s_v + c * VPL + oy * VP + cb + (h << 1);
            float2 u0 = *(const float2*)(p);
            float2 v0 = *(const float2*)(p + 2);
            float2 u1 = *(const float2*)(p + VP);
            float2 v1 = *(const float2*)(p + VP + 2);
            float2 u2 = *(const float2*)(p + 2*VP);
            float2 v2 = *(const float2*)(p + 2*VP + 2);
            // j=0 window cols: u.x,u.y,v.x ; j=1 window cols: u.y,v.x,v.y
            float gx0 = (u0.x - v0.x) + 2.f * (u1.x - v1.x) + (u2.x - v2.x);
            float gy0 = (u0.x - u2.x) + 2.f * (u0.y - u2.y) + (v0.x - v2.x);
            float gx1 = (u0.y - v0.y) + 2.f * (u1.y - v1.y) + (u2.y - v2.y);
            float gy1 = (u0.y - u2.y) + 2.f * (v0.x - v2.x) + (v0.y - v2.y);
            m0 += sqrtf(gx0 * gx0 + gy0 * gy0); ax0 += gx0; ay0 += gy0;
            m1 += sqrtf(gx1 * gx1 + gy1 * gy1); ax1 += gx1; ay1 += gy1;
        }
        float deg = atan2f(ay0, ax0) * (float)(180.0 / M_PI) + 180.f;
        ixi[2*h]     = ((int)rintf(deg / 45.f)) & 7;
        mgv[2*h]     = m0;
        deg = atan2f(ay1, ax1) * (float)(180.0 / M_PI) + 180.f;
        ixi[2*h + 1] = ((int)rintf(deg / 45.f)) & 7;
        mgv[2*h + 1] = m1;
    }

    size_t o = (size_t)b * HW + (size_t)(ty0 + oy) * WW + (tx0 + cb);
    *(float4*)(d_gm + o) = make_float4(mgv[0], mgv[1], mgv[2], mgv[3]);
    *(uchar4*)(d_dir + o) = make_uchar4((unsigned char)ixi[0], (unsigned char)ixi[1],
                                        (unsigned char)ixi[2], (unsigned char)ixi[3]);
}

// ---------------------------------------------------------------------------
// K2: NMS + hysteresis. 32x32 tile x 8 batches, 1024 threads, no div/mod,
// b-loop unrolled (literal offsets), plane stride 1344 (mult of 32) so the
// id-scattered NMS loads are bank-conflict-free. Zero-padded s_g makes the
// explicit OOB branches unnecessary (tval = ctr = 0 falls out).
// ---------------------------------------------------------------------------
#define TS 32
#define GT 36
#define GP 37
#define PL 1344                        // padded plane stride (36*37=1332 used)
#define TT 34
#define TP 35
#define SMEM2 ((8*PL + 8*TT*TP) * (int)sizeof(float))   // 81,088 B

__global__ __launch_bounds__(1024, 2)
void canny_thin(float* __restrict__ out)
{
    float* s_g = smem_dyn;              // 8 planes, stride PL, [36][37] each
    float* s_t = smem_dyn + 8 * PL;     // [8][34][35]

    const int tid = threadIdx.x;
    const int x = tid & 31, y = tid >> 5;
    const int ty0 = blockIdx.y * TS;
    const int tx0 = blockIdx.x * TS;

    const int OY[8] = {0, 1, 1, 1, 0, -1, -1, -1};
    const int OX[8] = {1, 1, 0, -1, -1, -1, 0, 1};

    // ---- load gm tiles, all 8 batches (zero-padded OOB) ----
    #pragma unroll
    for (int b = 0; b < 8; ++b) {
        const float* gmb = d_gm + (size_t)b * HW;
        float* sg = s_g + b * PL;
        #pragma unroll
        for (int rr = 0; rr < 2; ++rr) {
            int r = y + (rr << 5);
            if (rr == 0 || y < 4) {
                int gh = ty0 - 2 + r;
                bool rok = (unsigned)gh < HH;
                int gxx = tx0 - 2 + x;
                sg[r*GP + x] = (rok && (unsigned)gxx < WW)
                                 ? gmb[(size_t)gh * WW + gxx] : 0.f;
                if (x < 4) {
                    int q = x + 32; gxx = tx0 - 2 + q;
                    sg[r*GP + q] = (rok && (unsigned)gxx < WW)
                                     ? gmb[(size_t)gh * WW + gxx] : 0.f;
                }
            }
        }
    }
    __syncthreads();

    // ---- NMS: 8 x 34 x 34 (tile + 1 halo) ----
    #pragma unroll
    for (int b = 0; b < 8; ++b) {
        const unsigned char* dirb = d_dir + (size_t)b * HW;
        float* st = s_t + b * (TT * TP);
        #pragma unroll
        for (int rr = 0; rr < 2; ++rr) {
            int r = y + (rr << 5);
            bool rgo = (rr == 0) || (y < 2);
            #pragma unroll
            for (int qq = 0; qq < 2; ++qq) {
                int q = x + (qq << 5);
                bool qgo = (qq == 0) || (x < 2);
                if (rgo && qgo) {
                    int gh = ty0 - 1 + r, gxx = tx0 - 1 + q;
                    int ghc = min(max(gh, 0), HH - 1);
                    int gxc = min(max(gxx, 0), WW - 1);
                    int id  = dirb[(size_t)ghc * WW + gxc];
                    int ip  = id * PL;
                    int in_ = ((id + 4) & 7) * PL;
                    int o   = (r + 1) * GP + (q + 1);
                    int on  = o + OY[b] * GP + OX[b];
                    float cp  = s_g[ip  + o];
                    float cn  = s_g[in_ + o];
                    float np  = s_g[ip  + on];
                    float nn  = s_g[in_ + on];
                    float ctr = s_g[b * PL + o];
                    st[r*TP + q] = (fminf(cp - np, cn - nn) > 0.f) ? ctr : 0.f;
                }
            }
        }
    }
    __syncthreads();

    // ---- hysteresis + border zero ----
    const int gh  = ty0 + y, gxx = tx0 + x;
    const bool inter = (gh > 0) & (gh < HH - 1) & (gxx > 0) & (gxx < WW - 1);
    #pragma unroll
    for (int b = 0; b < 8; ++b) {
        const float* tp = s_t + b * (TT * TP) + y * TP + x;
        float tc = tp[TP + 1];
        bool res = (tc > 5.0f);
        if (!res && tc >= 2.5f) {
            res = tp[0]      > 5.f || tp[1]        > 5.f || tp[2]        > 5.f ||
                  tp[TP]     > 5.f || tp[TP + 2]   > 5.f ||
                  tp[2*TP]   > 5.f || tp[2*TP + 1] > 5.f || tp[2*TP + 2] > 5.f;
        }
        __stcs(&out[(size_t)b * HW + (size_t)gh * WW + gxx],
               (res && inter) ? 1.0f : 0.0f);
    }
}

// ---------------------------------------------------------------------------
extern "C" void kernel_launch(void* const* d_in, const int* in_sizes, int n_in,
                              void* d_out, int out_size)
{
    const float* img = (const float*)d_in[0];
    const float* gw  = (const float*)d_in[1];   // gauss_h weights (5 floats)
    float* out = (float*)d_out;

    cudaFuncSetAttribute(canny_grad, cudaFuncAttributeMaxDynamicSharedMemorySize, SMEM1);
    cudaFuncSetAttribute(canny_thin, cudaFuncAttributeMaxDynamicSharedMemorySize, SMEM2);

    dim3 g1(WW / T1, HH / T1, BQ);     // 16 x 16 x 8
    canny_grad<<<g1, 1024, SMEM1>>>(img, gw);

    dim3 g2(WW / TS, HH / TS, 1);      // 32 x 32
    canny_thin<<<g2, 1024, SMEM2>>>(out);
}